// round 8
// baseline (speedup 1.0000x reference)
#include <cuda_runtime.h>

// FlowNetC correlation on GB300 — round 8: pre-converted/de-interleaved tf32
// gmem scratch + cp.async 3-stage ring + 3 blocks/SM banded MMA.
//
// out[b, dy*21+dx, y, x] = (1/256) * sum_c in1[b,c,y,x] * in2[b,c, y+2dy-20, x+2dx-20]
//
// Kernel 1 (prepass): in1/in2 -> rna-tf32 bits, parity de-interleaved rows
//   [b][c][y][par][64]; A pre-scaled by 1/256 (exact).
// Kernel 2 (main): block = (dyg of 3 dy, y, b), 6 warps = 3 dy x 2 par,
//   __launch_bounds__(192,3). Per warp: 4 m16 x 5 n8 band tiles x 32 k8 steps
//   of mma.m16n8k8.tf32. Producer = pure cp.async (no pf regs), 3-stage smem,
//   1 wait_group + 1 barrier per chunk. Consumer = conflict-free LDS -> MMA.

#define DD      21
#define HH      96
#define WW      128
#define C_TOT   256
#define CKT     8
#define NCH     32
#define NDY     3
#define NTH     192

#define ULEN    104                 // B row words (==8 mod 32; reads [2,90))
#define B_WORDS (48 * ULEN)         // 3 dyl * 2 par * 8 c = 4992
#define ALEN    72                  // A row words (==8 mod 32)
#define A_BASE  B_WORDS
#define STAGE   (B_WORDS + 16 * ALEN)   // 6144 words
#define NSTG    3
#define SMEM_WORDS (NSTG * STAGE)       // 18432 words = 73728 B

#define ELEMS   (8 * 256 * 96 * 128)
#define TOT4    (ELEMS / 4)             // 6291456 float4 per tensor
#define CSTEP   (CKT * HH * WW)         // 98304 floats per chunk

__device__ float g1t[ELEMS];   // de-interleaved tf32 bits of in1 * (1/256)
__device__ float g2t[ELEMS];   // de-interleaved tf32 bits of in2

__device__ __forceinline__ unsigned cvt_tf32(float v) {
    unsigned r;
    asm("cvt.rna.tf32.f32 %0, %1;" : "=r"(r) : "f"(v));
    return r;
}
__device__ __forceinline__ void cp16(unsigned dst, const float* src) {
    asm volatile("cp.async.cg.shared.global [%0], [%1], 16;"
                 :: "r"(dst), "l"(src));
}
__device__ __forceinline__ void mma_tf32(float (&d)[4],
                                         unsigned a0, unsigned a1,
                                         unsigned a2, unsigned a3,
                                         unsigned b0, unsigned b1) {
    asm volatile(
        "mma.sync.aligned.m16n8k8.row.col.f32.tf32.tf32.f32 "
        "{%0,%1,%2,%3}, {%4,%5,%6,%7}, {%8,%9}, {%0,%1,%2,%3};"
        : "+f"(d[0]), "+f"(d[1]), "+f"(d[2]), "+f"(d[3])
        : "r"(a0), "r"(a1), "r"(a2), "r"(a3), "r"(b0), "r"(b1));
}

// ---- prepass: cvt.rna.tf32 + parity de-interleave ([..y][par 2][xh 64]) ----
__global__ void __launch_bounds__(256) prepass(const float* __restrict__ s1,
                                               const float* __restrict__ s2)
{
    unsigned i = blockIdx.x * 256u + threadIdx.x;   // float4 index
    if (i >= TOT4) return;
    const bool isA = (blockIdx.y == 0);
    float4 v = isA ? ((const float4*)s1)[i] : ((const float4*)s2)[i];
    const float sc = isA ? (1.0f / 256.0f) : 1.0f;  // exact scale, baked into A
    unsigned e0 = cvt_tf32(v.x * sc), o0 = cvt_tf32(v.y * sc);
    unsigned e1 = cvt_tf32(v.z * sc), o1 = cvt_tf32(v.w * sc);
    unsigned row = i >> 5, col4 = i & 31;           // row of 128 floats
    float* dst = (isA ? g1t : g2t) + (size_t)row * 128;
    ((uint2*)dst)[col4]        = make_uint2(e0, e1);   // even parity, xh=2col4..
    ((uint2*)(dst + 64))[col4] = make_uint2(o0, o1);   // odd parity
}

extern __shared__ unsigned smw[];

__global__ void __launch_bounds__(NTH, 3) corr_mma(float* __restrict__ g_out)
{
    const int b    = blockIdx.z;
    const int y    = blockIdx.y;
    const int dyg  = blockIdx.x;      // 0..6
    const int dy0  = dyg * NDY;
    const int tid  = threadIdx.x;
    const int lane = tid & 31;
    const int w    = tid >> 5;        // 0..5
    const int dyl  = w >> 1;          // 0..2
    const int par  = w & 1;
    const int g    = lane >> 2;       // 0..7
    const int t    = lane & 3;        // 0..3

    const size_t plane = (size_t)HH * WW;

    // Zero all stages once: pads + OOB-dy rows stay zero forever
    // (cp.async only ever writes the valid interiors).
    for (int i = tid; i < SMEM_WORDS; i += NTH) smw[i] = 0u;

    const unsigned sm0 = (unsigned)__cvta_generic_to_shared(smw);

    // ---- cp.async slots. B: 48 rows x 16 chunks = 768 (4/thread).
    //      A: 16 rows x 16 chunks = 256 (slot4 all, slot5 tid<64). ----
    unsigned boff[4], bdst[4];
    bool     bok[4];
    #pragma unroll
    for (int q = 0; q < 4; ++q) {
        int idx = q * NTH + tid;          // 0..767
        int ch  = idx & 15;
        int row = idx >> 4;               // 0..47
        int dl  = row >> 4;               // 0..2
        int pr  = (row >> 3) & 1;
        int c   = row & 7;
        int row2 = y + 2 * (dy0 + dl) - 20;
        bok[q]  = (row2 >= 0) && (row2 < HH);
        boff[q] = (unsigned)(((b * C_TOT + c) * HH + (bok[q] ? row2 : 0)) * WW
                             + pr * 64 + ch * 4);
        bdst[q] = sm0 + (unsigned)((row * ULEN) + 12 + ch * 4) * 4u;
    }
    unsigned aoff0, aoff1, adst0, adst1;
    const bool a1act = (tid < 64);
    {
        int idx = tid;                    // slot 4
        int ch = idx & 15, row = idx >> 4;          // row 0..11
        aoff0 = (unsigned)(((b * C_TOT + (row & 7)) * HH + y) * WW
                           + (row >> 3) * 64 + ch * 4);
        adst0 = sm0 + (unsigned)(A_BASE + row * ALEN + ch * 4) * 4u;
        idx = NTH + tid;                  // slot 5 (rows 12..15), tid<64
        ch = idx & 15; row = idx >> 4;
        aoff1 = (unsigned)(((b * C_TOT + (row & 7)) * HH + y) * WW
                           + (row >> 3) * 64 + ch * 4);
        adst1 = sm0 + (unsigned)(A_BASE + row * ALEN + ch * 4) * 4u;
    }

    float acc[20][4];
    #pragma unroll
    for (int f = 0; f < 20; ++f)
        #pragma unroll
        for (int e = 0; e < 4; ++e) acc[f][e] = 0.0f;

    __syncthreads();   // zeroing done before first cp.async lands

    auto issue_chunk = [&](unsigned sbyte) {
        #pragma unroll
        for (int q = 0; q < 4; ++q) {
            if (bok[q]) cp16(bdst[q] + sbyte, (const float*)g2t + boff[q]);
            boff[q] += CSTEP;
        }
        cp16(adst0 + sbyte, (const float*)g1t + aoff0);  aoff0 += CSTEP;
        if (a1act) { cp16(adst1 + sbyte, (const float*)g1t + aoff1); aoff1 += CSTEP; }
    };

    // prologue: chunks 0 and 1 in flight
    issue_chunk(0u);
    asm volatile("cp.async.commit_group;");
    issue_chunk(STAGE * 4u);
    asm volatile("cp.async.commit_group;");

    const int browbase = (dyl * 2 + par) * 8 * ULEN;
    const int arowbase = A_BASE + par * 8 * ALEN;

    int sg_c = 0, sg_i = 2;
    for (int k = 0; k < NCH; ++k) {
        // committed = k+2 groups; allow 1 pending -> group k (chunk k) done
        asm volatile("cp.async.wait_group 1;");
        __syncthreads();   // all threads' chunk-k data visible; all done compute k-1

        if (k + 2 < NCH) issue_chunk((unsigned)(sg_i * STAGE) * 4u);
        asm volatile("cp.async.commit_group;");    // keep group count uniform

        // ---- compute chunk k: conflict-free LDS -> MMA (mt-outer) ----
        const unsigned* Bw = smw + sg_c * STAGE + browbase;   // [c][ULEN]
        const unsigned* Aw = smw + sg_c * STAGE + arowbase;   // [c][ALEN]
        #pragma unroll
        for (int mt = 0; mt < 4; ++mt) {
            const int m0 = 16 * mt + g;
            unsigned a0 = Aw[t * ALEN + m0];
            unsigned a1 = Aw[t * ALEN + m0 + 8];
            unsigned a2 = Aw[(t + 4) * ALEN + m0];
            unsigned a3 = Aw[(t + 4) * ALEN + m0 + 8];
            #pragma unroll
            for (int i = 0; i < 5; ++i) {
                const int u = 8 * (2 * mt + i) + g + 2;   // data at +12, reads [2,90)
                unsigned b0 = Bw[t * ULEN + u];
                unsigned b1 = Bw[(t + 4) * ULEN + u];
                mma_tf32(acc[mt * 5 + i], a0, a1, a2, a3, b0, b1);
            }
        }
        sg_c = (sg_c == 2) ? 0 : sg_c + 1;
        sg_i = (sg_i == 2) ? 0 : sg_i + 1;
    }

    // ---- epilogue: band-extract + scatter stores (scale pre-baked in A) ----
    const int dy = dy0 + dyl;
    float* ob = g_out + ((size_t)(b * (DD * DD) + dy * DD)) * plane
                      + (size_t)y * WW + par;
    #pragma unroll
    for (int mt = 0; mt < 4; ++mt) {
        #pragma unroll
        for (int i = 0; i < 5; ++i) {
            const int u0 = 8 * (2 * mt + i);
            const float* f = acc[mt * 5 + i];
            #pragma unroll
            for (int e = 0; e < 4; ++e) {
                int r   = (e >= 2) ? (g + 8) : g;
                int col = 2 * t + (e & 1);
                int xh  = 16 * mt + r;
                int dx  = u0 + col - xh;
                if (dx >= 0 && dx < DD)
                    ob[(size_t)dx * plane + 2 * xh] = f[e];
            }
        }
    }
}

extern "C" void kernel_launch(void* const* d_in, const int* in_sizes, int n_in,
                              void* d_out, int out_size)
{
    (void)in_sizes; (void)n_in; (void)out_size;
    const float* in1 = (const float*)d_in[0];
    const float* in2 = (const float*)d_in[1];
    float*       out = (float*)d_out;

    // kernel 1: convert + de-interleave both tensors
    prepass<<<dim3(TOT4 / 256, 2), 256>>>(in1, in2);

    // kernel 2: banded MMA
    cudaFuncSetAttribute(corr_mma, cudaFuncAttributeMaxDynamicSharedMemorySize,
                         SMEM_WORDS * 4);
    dim3 grid(7, HH, 8);     // (dy-group of 3, y, b) -> 5376 blocks
    corr_mma<<<grid, NTH, SMEM_WORDS * 4>>>(out);
}

// round 9
// speedup vs baseline: 1.5972x; 1.5972x over previous
#include <cuda_runtime.h>

// FlowNetC correlation on GB300 — round 9: ldmatrix.x4 fragment loads from
// k-contiguous tf32 scratch, cp.async 4-stage ring, banded m16n8k8 MMA.
//
// out[b, dy*21+dx, y, x] = (1/256) * sum_c in1[b,c,y,x] * in2[b,c, y+2dy-20, x+2dx-20]
//
// Prepass: both inputs -> rna-tf32 bits in layout [b][c4][y][par][xh][cc4]
// (16B unit = 4 consecutive channels for one (par,xh)); A pre-scaled by 1/256.
// Main: block = (dyg of 3 dy, y, b), 6 warps = (dyl, par); per warp 4 m16 x
// 5-band n8 x 32 k8 MMAs. Fragments via ldmatrix.x4: each 8-row phase is a
// contiguous 128B smem line (conflict-free, no padding).

#define DD      21
#define HH      96
#define WW      128
#define NCH     32
#define NDY     3
#define NTH     192

// smem (words). B: [dl 3][par 2][kh 2][u 96][4]; A: [par 2][kh 2][m 64][4]
#define B_KH    384                 // 96 rows * 4 words
#define B_DP    768                 // 2 kh per (dl,par)
#define B_WORDS 4608
#define A_BASE  4608
#define STAGE   5632                // + A: 2*2*64*4 = 1024
#define NSTG    4
#define SMEM_WORDS (NSTG * STAGE)   // 22528 words = 90112 B
#define STAGE_B (STAGE * 4)

#define ELEMS   (8 * 256 * 96 * 128)
#define CSTEP   (2 * 96 * 2 * 64 * 4)   // +2 c4 per chunk = 98304 floats

__device__ float g1t[ELEMS];   // A scratch (in1 * 1/256, tf32 bits)
__device__ float g2t[ELEMS];   // B scratch (in2, tf32 bits)

__device__ __forceinline__ unsigned cvt_tf32(float v) {
    unsigned r;
    asm("cvt.rna.tf32.f32 %0, %1;" : "=r"(r) : "f"(v));
    return r;
}
__device__ __forceinline__ void cp16(unsigned dst, const float* src) {
    asm volatile("cp.async.cg.shared.global [%0], [%1], 16;"
                 :: "r"(dst), "l"(src));
}
__device__ __forceinline__ void ldsm4(unsigned addr, unsigned& r0, unsigned& r1,
                                      unsigned& r2, unsigned& r3) {
    asm volatile("ldmatrix.sync.aligned.m8n8.x4.shared.b16 {%0,%1,%2,%3}, [%4];"
                 : "=r"(r0), "=r"(r1), "=r"(r2), "=r"(r3) : "r"(addr));
}
__device__ __forceinline__ void mma_tf32(float (&d)[4],
                                         unsigned a0, unsigned a1,
                                         unsigned a2, unsigned a3,
                                         unsigned b0, unsigned b1) {
    asm volatile(
        "mma.sync.aligned.m16n8k8.row.col.f32.tf32.tf32.f32 "
        "{%0,%1,%2,%3}, {%4,%5,%6,%7}, {%8,%9}, {%0,%1,%2,%3};"
        : "+f"(d[0]), "+f"(d[1]), "+f"(d[2]), "+f"(d[3])
        : "r"(a0), "r"(a1), "r"(a2), "r"(a3), "r"(b0), "r"(b1));
}

// ---- prepass: cvt + transpose to [b][c4][y][par][xh][cc4] (uint4 stores) ----
__global__ void __launch_bounds__(128) prepass(const float* __restrict__ s1,
                                               const float* __restrict__ s2)
{
    const int x   = threadIdx.x;        // 0..127
    const int y   = blockIdx.x;         // 96
    const int c4  = blockIdx.y;         // 64
    const int b   = blockIdx.z & 7;
    const bool isA = blockIdx.z >= 8;
    const size_t plane = (size_t)HH * WW;
    const float* src = (isA ? s1 : s2)
        + ((size_t)(b * 256 + c4 * 4) * HH + y) * WW + x;
    const float sc = isA ? (1.0f / 256.0f) : 1.0f;   // exact, baked into A
    unsigned v0 = cvt_tf32(src[0]         * sc);
    unsigned v1 = cvt_tf32(src[plane]     * sc);
    unsigned v2 = cvt_tf32(src[2 * plane] * sc);
    unsigned v3 = cvt_tf32(src[3 * plane] * sc);
    float* dstT = isA ? g1t : g2t;
    size_t o = ((((size_t)b * 64 + c4) * HH + y) * 2 + (x & 1)) * 64 + (x >> 1);
    ((uint4*)dstT)[o] = make_uint4(v0, v1, v2, v3);
}

extern __shared__ unsigned smw[];

__global__ void __launch_bounds__(NTH, 2) corr_mma(float* __restrict__ g_out)
{
    const int b    = blockIdx.z;
    const int y    = blockIdx.y;
    const int dyg  = blockIdx.x;      // 0..6
    const int dy0  = dyg * NDY;
    const int tid  = threadIdx.x;
    const int lane = tid & 31;
    const int w    = tid >> 5;        // 0..5 == (dyl*2 + par)
    const int par  = w & 1;
    const int g    = lane >> 2;
    const int t    = lane & 3;

    const size_t plane = (size_t)HH * WW;

    // Zero all stages once: pad rows (u<10, u>=74) and OOB-dy rows stay zero.
    for (int i = tid; i < SMEM_WORDS; i += NTH) smw[i] = 0u;

    const unsigned sm0 = (unsigned)__cvta_generic_to_shared(smw);

    // ---- cp.async slots. B: 768 16B-rows/chunk (4/thread); A: 256 (slot4 + tid<64)
    unsigned boff[4], bdstB[4];
    bool     bok[4];
    #pragma unroll
    for (int q = 0; q < 4; ++q) {
        int idx = q * NTH + tid;          // 0..767
        int u6  = idx & 63;
        int kh  = (idx >> 6) & 1;
        int pr  = (idx >> 7) & 1;
        int dl  = idx >> 8;               // 0..2
        int row2 = y + 2 * (dy0 + dl) - 20;
        bok[q]  = (row2 >= 0) && (row2 < HH);
        boff[q] = (unsigned)(((((b * 64 + kh) * HH + (bok[q] ? row2 : 0)) * 2 + pr)
                              * 64 + u6) * 4);
        bdstB[q] = sm0 + (unsigned)(((dl * 2 + pr) * B_DP + kh * B_KH
                                     + (u6 + 10) * 4) * 4);
    }
    unsigned aoff[2], adstB[2];
    #pragma unroll
    for (int q = 0; q < 2; ++q) {
        int idx = q * NTH + tid;          // valid when idx < 256
        int m   = idx & 63;
        int kh  = (idx >> 6) & 1;
        int pr  = (idx >> 7) & 1;
        aoff[q]  = (unsigned)(((((b * 64 + kh) * HH + y) * 2 + pr) * 64 + m) * 4);
        adstB[q] = sm0 + (unsigned)((A_BASE + pr * 512 + kh * 256 + m * 4) * 4);
    }
    const bool a1act = (tid < 64);

    // ---- ldmatrix lane bases (byte addresses into stage 0) ----
    // B x4 for jp: grp0/1 = (kh0/kh1, u=16jp+r), grp2/3 = (kh0/kh1, u+8)
    const unsigned bl_kh = (lane >> 3) & 1;
    const unsigned bl_u  = ((lane >> 4) << 3) + (lane & 7);
    const unsigned bLds  = sm0 + (w * B_DP + bl_kh * B_KH + bl_u * 4) * 4;
    // A x4 for mt: grp0/1 = (kh0, m+r / m+8+r), grp2/3 = (kh1, ...)
    const unsigned al_kh = lane >> 4;
    const unsigned al_m  = ((lane >> 3) & 1) * 8 + (lane & 7);
    const unsigned aLds  = sm0 + (A_BASE + par * 512 + al_kh * 256 + al_m * 4) * 4;

    float acc[20][4];
    #pragma unroll
    for (int f = 0; f < 20; ++f)
        #pragma unroll
        for (int e = 0; e < 4; ++e) acc[f][e] = 0.0f;

    __syncthreads();   // zeroing complete before any cp.async lands

    auto issue_chunk = [&](int stg) {
        const unsigned sb = (unsigned)stg * STAGE_B;
        #pragma unroll
        for (int q = 0; q < 4; ++q) {
            if (bok[q]) cp16(bdstB[q] + sb, (const float*)g2t + boff[q]);
            boff[q] += CSTEP;
        }
        cp16(adstB[0] + sb, (const float*)g1t + aoff[0]);  aoff[0] += CSTEP;
        if (a1act) { cp16(adstB[1] + sb, (const float*)g1t + aoff[1]); aoff[1] += CSTEP; }
    };

    issue_chunk(0); asm volatile("cp.async.commit_group;");
    issue_chunk(1); asm volatile("cp.async.commit_group;");
    issue_chunk(2); asm volatile("cp.async.commit_group;");

    for (int k = 0; k < NCH; ++k) {
        asm volatile("cp.async.wait_group 2;");   // chunk k complete
        __syncthreads();  // visible to all; all warps finished compute k-1

        if (k + 3 < NCH) issue_chunk((k + 3) & 3);
        asm volatile("cp.async.commit_group;");   // uniform group counting

        const unsigned sb = (unsigned)(k & 3) * STAGE_B;

        // A fragments: 4 ldmatrix.x4 (one per m16 tile)
        unsigned a[4][4];
        #pragma unroll
        for (int mt = 0; mt < 4; ++mt)
            ldsm4(aLds + sb + mt * 256, a[mt][0], a[mt][1], a[mt][2], a[mt][3]);

        // B fragments + MMAs: 6 ldmatrix.x4 (each covers j=2jp, 2jp+1)
        #pragma unroll
        for (int jp = 0; jp < 6; ++jp) {
            unsigned b0, b1, b2, b3;
            ldsm4(bLds + sb + jp * 256, b0, b1, b2, b3);
            const int j0 = 2 * jp;
            #pragma unroll
            for (int mt = 0; mt < 4; ++mt)
                if (2 * mt <= j0 && j0 <= 2 * mt + 4)
                    mma_tf32(acc[mt * 5 + (j0 - 2 * mt)],
                             a[mt][0], a[mt][1], a[mt][2], a[mt][3], b0, b1);
            const int j1 = j0 + 1;
            if (j1 < 11) {
                #pragma unroll
                for (int mt = 0; mt < 4; ++mt)
                    if (2 * mt <= j1 && j1 <= 2 * mt + 4)
                        mma_tf32(acc[mt * 5 + (j1 - 2 * mt)],
                                 a[mt][0], a[mt][1], a[mt][2], a[mt][3], b2, b3);
            }
        }
    }

    // ---- epilogue: band-extract + scatter stores (1/256 pre-baked in A) ----
    const int dy = dy0 + (w >> 1);
    float* ob = g_out + ((size_t)(b * (DD * DD) + dy * DD)) * plane
                      + (size_t)y * WW + par;
    #pragma unroll
    for (int mt = 0; mt < 4; ++mt) {
        #pragma unroll
        for (int i = 0; i < 5; ++i) {
            const int u0 = 8 * (2 * mt + i);
            const float* f = acc[mt * 5 + i];
            #pragma unroll
            for (int e = 0; e < 4; ++e) {
                int r   = (e >= 2) ? (g + 8) : g;
                int col = 2 * t + (e & 1);
                int xh  = 16 * mt + r;
                int dx  = u0 + col - xh;
                if (dx >= 0 && dx < DD)
                    ob[(size_t)dx * plane + 2 * xh] = f[e];
            }
        }
    }
}

extern "C" void kernel_launch(void* const* d_in, const int* in_sizes, int n_in,
                              void* d_out, int out_size)
{
    (void)in_sizes; (void)n_in; (void)out_size;
    const float* in1 = (const float*)d_in[0];
    const float* in2 = (const float*)d_in[1];
    float*       out = (float*)d_out;

    // kernel 1: convert + transpose both tensors into k-contiguous scratch
    prepass<<<dim3(HH, 64, 16), 128>>>(in1, in2);

    // kernel 2: banded MMA
    cudaFuncSetAttribute(corr_mma, cudaFuncAttributeMaxDynamicSharedMemorySize,
                         SMEM_WORDS * 4);
    dim3 grid(7, HH, 8);     // (dy-group of 3, y, b) -> 5376 blocks
    corr_mma<<<grid, NTH, SMEM_WORDS * 4>>>(out);
}